// round 1
// baseline (speedup 1.0000x reference)
#include <cuda_runtime.h>
#include <cuda_bf16.h>

#define NN 50000
#define EE 800000
#define DD 128
#define OO 64
#define LL 3

// ---------------- scratch (device globals; no allocation allowed) ----------
__device__ float g_h0[NN * DD];
__device__ float g_h1[NN * DD];
__device__ float g_agg0[NN * DD];   // (1-a)/deg * sum_{src->dst}
__device__ float g_agg1[NN * DD];   // a/deg * sum_{dst->src}
__device__ float g_hmax[NN * DD];

__device__ int g_deg0[NN];          // in-degree (keyed by dst)
__device__ int g_deg1[NN];          // out-degree (keyed by src)
__device__ int g_rp0[NN + 1];
__device__ int g_rp1[NN + 1];
__device__ int g_cur0[NN];
__device__ int g_cur1[NN];
__device__ int g_col0[EE];          // CSR by dst, values = src
__device__ int g_col1[EE];          // CSR by src, values = dst

// ---------------- CSR build ----------------
__global__ void zero_deg_kernel(int n) {
    int i = blockIdx.x * blockDim.x + threadIdx.x;
    if (i < n) { g_deg0[i] = 0; g_deg1[i] = 0; }
}

__global__ void count_kernel(const int* __restrict__ ei, int E) {
    int e = blockIdx.x * blockDim.x + threadIdx.x;
    if (e >= E) return;
    int src = ei[e];
    int dst = ei[E + e];
    atomicAdd(&g_deg0[dst], 1);
    atomicAdd(&g_deg1[src], 1);
}

// one block per direction; blockDim = 1024
__global__ void scan_kernel(int n) {
    const int* deg = (blockIdx.x == 0) ? g_deg0 : g_deg1;
    int* rp = (blockIdx.x == 0) ? g_rp0 : g_rp1;
    int* cur = (blockIdx.x == 0) ? g_cur0 : g_cur1;

    __shared__ int sums[1024];
    int t = threadIdx.x;
    int chunk = (n + 1023) / 1024;
    int begin = t * chunk;
    int end = min(begin + chunk, n);
    int s = 0;
    for (int i = begin; i < end; i++) s += deg[i];
    sums[t] = s;
    __syncthreads();
    // Hillis-Steele inclusive scan
    for (int off = 1; off < 1024; off <<= 1) {
        int v = (t >= off) ? sums[t - off] : 0;
        __syncthreads();
        sums[t] += v;
        __syncthreads();
    }
    int prefix = (t == 0) ? 0 : sums[t - 1];
    for (int i = begin; i < end; i++) {
        rp[i] = prefix;
        cur[i] = prefix;
        prefix += deg[i];
    }
    if (t == 1023) rp[n] = prefix;
}

__global__ void fill_kernel(const int* __restrict__ ei, int E) {
    int e = blockIdx.x * blockDim.x + threadIdx.x;
    if (e >= E) return;
    int src = ei[e];
    int dst = ei[E + e];
    int p0 = atomicAdd(&g_cur0[dst], 1);
    g_col0[p0] = src;
    int p1 = atomicAdd(&g_cur1[src], 1);
    g_col1[p1] = dst;
}

// ---------------- aggregation: one node per block, 128 threads ----------------
__global__ void agg_kernel(const float* __restrict__ h,
                           const float* __restrict__ alpha) {
    int n = blockIdx.x;
    int d = threadIdx.x;
    float a = alpha[0];

    int s = g_rp0[n], e = g_rp0[n + 1];
    float acc = 0.f;
    for (int i = s; i < e; i++) acc += h[g_col0[i] * DD + d];
    float deg = fmaxf((float)(e - s), 1.f);
    g_agg0[n * DD + d] = acc * ((1.f - a) / deg);

    s = g_rp1[n]; e = g_rp1[n + 1];
    acc = 0.f;
    for (int i = s; i < e; i++) acc += h[g_col1[i] * DD + d];
    deg = fmaxf((float)(e - s), 1.f);
    g_agg1[n * DD + d] = acc * (a / deg);
}

// ---------------- fused layer GEMM: [h|agg0|agg1] (Mx384) @ [Wself;Wstd;Wdts] (384x128)
// BM=64, BN=128, BK=16, 256 threads, 8x4 microtile. Epilogue: +bias, relu, JK-max.
__global__ __launch_bounds__(256) void gemm_layer_kernel(
    const float* __restrict__ A0,  // h (or x)
    const float* __restrict__ B0,  // Wself[layer]
    const float* __restrict__ B1,  // Wstd[layer]
    const float* __restrict__ B2,  // Wdts[layer]
    const float* __restrict__ bs0, // bself[layer]
    const float* __restrict__ bs1, // bstd[layer]
    const float* __restrict__ bs2, // bdts[layer]
    const float* __restrict__ alpha,
    float* __restrict__ Hout,
    int firstLayer, int M)
{
    __shared__ __align__(16) float As[16][64];
    __shared__ __align__(16) float Bs[16][128];

    int tid = threadIdx.x;
    int block_row = blockIdx.x * 64;
    int tx = tid & 31;   // col group (4 cols)
    int ty = tid >> 5;   // row group (8 rows)

    float acc[8][4];
    #pragma unroll
    for (int i = 0; i < 8; i++)
        #pragma unroll
        for (int j = 0; j < 4; j++) acc[i][j] = 0.f;

    const float* Aseg[3] = { A0, g_agg0, g_agg1 };
    const float* Bseg[3] = { B0, B1, B2 };

    int a_row = tid >> 2;        // 0..63
    int a_f4 = (tid & 3) * 4;    // 0,4,8,12

    #pragma unroll 1
    for (int chunk = 0; chunk < 24; chunk++) {
        int seg = chunk >> 3;
        int kl = (chunk & 7) * 16;
        const float* A = Aseg[seg];
        const float* B = Bseg[seg];

        // load A tile (64x16) transposed into As[k][m]
        int gr = block_row + a_row;
        float4 av = make_float4(0.f, 0.f, 0.f, 0.f);
        if (gr < M) av = *(const float4*)(A + (size_t)gr * DD + kl + a_f4);
        As[a_f4 + 0][a_row] = av.x;
        As[a_f4 + 1][a_row] = av.y;
        As[a_f4 + 2][a_row] = av.z;
        As[a_f4 + 3][a_row] = av.w;

        // load B tile (16x128): 512 float4 / 256 threads = 2 each
        #pragma unroll
        for (int i = 0; i < 2; i++) {
            int idx = tid + i * 256;
            int k = idx >> 5;
            int j = (idx & 31) * 4;
            float4 bv = *(const float4*)(B + (size_t)(kl + k) * DD + j);
            *(float4*)&Bs[k][j] = bv;
        }
        __syncthreads();

        #pragma unroll
        for (int kk = 0; kk < 16; kk++) {
            float af[8];
            #pragma unroll
            for (int i = 0; i < 8; i++) af[i] = As[kk][ty * 8 + i];
            float4 bv = *(const float4*)&Bs[kk][tx * 4];
            float bf[4] = { bv.x, bv.y, bv.z, bv.w };
            #pragma unroll
            for (int i = 0; i < 8; i++)
                #pragma unroll
                for (int j = 0; j < 4; j++)
                    acc[i][j] += af[i] * bf[j];
        }
        __syncthreads();
    }

    float a = alpha[0];
    #pragma unroll
    for (int j = 0; j < 4; j++) {
        int c = tx * 4 + j;
        float bias = bs0[c] + (1.f - a) * bs1[c] + a * bs2[c];
        #pragma unroll
        for (int i = 0; i < 8; i++) {
            int r = block_row + ty * 8 + i;
            if (r < M) {
                float v = acc[i][j] + bias;
                v = fmaxf(v, 0.f);
                Hout[(size_t)r * DD + c] = v;
                float m = firstLayer ? v : fmaxf(g_hmax[(size_t)r * DD + c], v);
                g_hmax[(size_t)r * DD + c] = m;
            }
        }
    }
}

// ---------------- final linear: hmax (Mx128) @ Wlin (128x64) + blin ----------------
// 16 rows per block, 256 threads: col = tid&63, rgrp = tid>>6, 4 rows per thread.
__global__ __launch_bounds__(256) void final_gemm_kernel(
    const float* __restrict__ W, const float* __restrict__ b,
    float* __restrict__ out, int M)
{
    __shared__ __align__(16) float Ws[DD * OO];   // 32KB
    __shared__ __align__(16) float As[16][DD];    // 8KB

    int tid = threadIdx.x;
    for (int i = tid; i < DD * OO / 4; i += 256)
        ((float4*)Ws)[i] = ((const float4*)W)[i];

    int row0 = blockIdx.x * 16;
    for (int i = tid; i < 16 * DD / 4; i += 256) {
        int r = i / 32;      // 32 float4 per row
        int c4 = i % 32;
        int gr = row0 + r;
        float4 v = make_float4(0.f, 0.f, 0.f, 0.f);
        if (gr < M) v = ((const float4*)(g_hmax + (size_t)gr * DD))[c4];
        ((float4*)&As[r][0])[c4] = v;
    }
    __syncthreads();

    int col = tid & 63;
    int rgrp = tid >> 6;   // 0..3
    float acc[4] = { 0.f, 0.f, 0.f, 0.f };
    #pragma unroll 4
    for (int k = 0; k < DD; k++) {
        float w = Ws[k * OO + col];
        #pragma unroll
        for (int i = 0; i < 4; i++)
            acc[i] += As[rgrp + i * 4][k] * w;
    }
    float bb = b[col];
    #pragma unroll
    for (int i = 0; i < 4; i++) {
        int r = row0 + rgrp + i * 4;
        if (r < M) out[(size_t)r * OO + col] = acc[i] + bb;
    }
}

// ---------------- launch ----------------
extern "C" void kernel_launch(void* const* d_in, const int* in_sizes, int n_in,
                              void* d_out, int out_size) {
    const float* x     = (const float*)d_in[0];
    const int*   ei    = (const int*)d_in[1];
    const float* Wself = (const float*)d_in[2];
    const float* bself = (const float*)d_in[3];
    const float* Wstd  = (const float*)d_in[4];
    const float* bstd  = (const float*)d_in[5];
    const float* Wdts  = (const float*)d_in[6];
    const float* bdts  = (const float*)d_in[7];
    const float* Wlin  = (const float*)d_in[8];
    const float* blin  = (const float*)d_in[9];
    const float* alpha = (const float*)d_in[10];

    int M = in_sizes[0] / DD;        // 50000
    int E = in_sizes[1] / 2;         // 800000

    float* h0; cudaGetSymbolAddress((void**)&h0, g_h0);
    float* h1; cudaGetSymbolAddress((void**)&h1, g_h1);

    // CSR build
    zero_deg_kernel<<<(M + 255) / 256, 256>>>(M);
    count_kernel<<<(E + 255) / 256, 256>>>(ei, E);
    scan_kernel<<<2, 1024>>>(M);
    fill_kernel<<<(E + 255) / 256, 256>>>(ei, E);

    // layers
    const float* cur = x;
    float* bufs[2] = { h0, h1 };
    int gemm_grid = (M + 63) / 64;
    for (int l = 0; l < LL; l++) {
        agg_kernel<<<M, DD>>>(cur, alpha);
        float* outb = bufs[l & 1];
        gemm_layer_kernel<<<gemm_grid, 256>>>(
            cur,
            Wself + (size_t)l * DD * DD,
            Wstd  + (size_t)l * DD * DD,
            Wdts  + (size_t)l * DD * DD,
            bself + (size_t)l * DD,
            bstd  + (size_t)l * DD,
            bdts  + (size_t)l * DD,
            alpha, outb, (l == 0) ? 1 : 0, M);
        cur = outb;
    }

    // final linear
    final_gemm_kernel<<<(M + 15) / 16, 256>>>(Wlin, blin, (float*)d_out, M);
}

// round 2
// speedup vs baseline: 1.4236x; 1.4236x over previous
#include <cuda_runtime.h>
#include <cuda_bf16.h>

#define NN 50000
#define EE 800000
#define DD 128
#define OO 64
#define LL 3

// ---------------- scratch (device globals; no allocation allowed) ----------
__device__ float g_h0[NN * DD];
__device__ float g_h1[NN * DD];
__device__ float g_agg0[NN * DD];   // (1-a)/deg * sum_{src->dst}
__device__ float g_agg1[NN * DD];   // a/deg * sum_{dst->src}
__device__ float g_hmax[NN * DD];

__device__ int g_deg0[NN];
__device__ int g_deg1[NN];
__device__ int g_rp0[NN + 1];
__device__ int g_rp1[NN + 1];
__device__ int g_cur0[NN];
__device__ int g_cur1[NN];
__device__ int g_col0[EE];          // CSR by dst, values = src
__device__ int g_col1[EE];          // CSR by src, values = dst

// ---------------- CSR build ----------------
__global__ void zero_deg_kernel(int n) {
    int i = blockIdx.x * blockDim.x + threadIdx.x;
    if (i < n) { g_deg0[i] = 0; g_deg1[i] = 0; }
}

__global__ void count_kernel(const int* __restrict__ ei, int E) {
    int e = blockIdx.x * blockDim.x + threadIdx.x;
    if (e >= E) return;
    int src = ei[e];
    int dst = ei[E + e];
    atomicAdd(&g_deg0[dst], 1);
    atomicAdd(&g_deg1[src], 1);
}

__global__ void scan_kernel(int n) {
    const int* deg = (blockIdx.x == 0) ? g_deg0 : g_deg1;
    int* rp = (blockIdx.x == 0) ? g_rp0 : g_rp1;
    int* cur = (blockIdx.x == 0) ? g_cur0 : g_cur1;

    __shared__ int sums[1024];
    int t = threadIdx.x;
    int chunk = (n + 1023) / 1024;
    int begin = t * chunk;
    int end = min(begin + chunk, n);
    int s = 0;
    for (int i = begin; i < end; i++) s += deg[i];
    sums[t] = s;
    __syncthreads();
    for (int off = 1; off < 1024; off <<= 1) {
        int v = (t >= off) ? sums[t - off] : 0;
        __syncthreads();
        sums[t] += v;
        __syncthreads();
    }
    int prefix = (t == 0) ? 0 : sums[t - 1];
    for (int i = begin; i < end; i++) {
        rp[i] = prefix;
        cur[i] = prefix;
        prefix += deg[i];
    }
    if (t == 1023) rp[n] = prefix;
}

__global__ void fill_kernel(const int* __restrict__ ei, int E) {
    int e = blockIdx.x * blockDim.x + threadIdx.x;
    if (e >= E) return;
    int src = ei[e];
    int dst = ei[E + e];
    int p0 = atomicAdd(&g_cur0[dst], 1);
    g_col0[p0] = src;
    int p1 = atomicAdd(&g_cur1[src], 1);
    g_col1[p1] = dst;
}

// ---------------- aggregation: one warp per node, float4 lanes ----------------
__global__ void agg_kernel(const float* __restrict__ h,
                           const float* __restrict__ alpha, int M) {
    int gw = (blockIdx.x * blockDim.x + threadIdx.x) >> 5;
    if (gw >= M) return;
    int lane = threadIdx.x & 31;
    int base = lane * 4;
    float a = alpha[0];

    // direction 0: neighbors by dst
    {
        int s = g_rp0[gw], e = g_rp0[gw + 1];
        float4 acc = make_float4(0.f, 0.f, 0.f, 0.f);
        int i = s;
        for (; i + 1 < e; i += 2) {
            int n0 = g_col0[i], n1 = g_col0[i + 1];
            float4 v0 = *(const float4*)(h + (size_t)n0 * DD + base);
            float4 v1 = *(const float4*)(h + (size_t)n1 * DD + base);
            acc.x += v0.x + v1.x; acc.y += v0.y + v1.y;
            acc.z += v0.z + v1.z; acc.w += v0.w + v1.w;
        }
        if (i < e) {
            int n0 = g_col0[i];
            float4 v0 = *(const float4*)(h + (size_t)n0 * DD + base);
            acc.x += v0.x; acc.y += v0.y; acc.z += v0.z; acc.w += v0.w;
        }
        float sc = (1.f - a) / fmaxf((float)(e - s), 1.f);
        acc.x *= sc; acc.y *= sc; acc.z *= sc; acc.w *= sc;
        *(float4*)(g_agg0 + (size_t)gw * DD + base) = acc;
    }
    // direction 1: neighbors by src
    {
        int s = g_rp1[gw], e = g_rp1[gw + 1];
        float4 acc = make_float4(0.f, 0.f, 0.f, 0.f);
        int i = s;
        for (; i + 1 < e; i += 2) {
            int n0 = g_col1[i], n1 = g_col1[i + 1];
            float4 v0 = *(const float4*)(h + (size_t)n0 * DD + base);
            float4 v1 = *(const float4*)(h + (size_t)n1 * DD + base);
            acc.x += v0.x + v1.x; acc.y += v0.y + v1.y;
            acc.z += v0.z + v1.z; acc.w += v0.w + v1.w;
        }
        if (i < e) {
            int n0 = g_col1[i];
            float4 v0 = *(const float4*)(h + (size_t)n0 * DD + base);
            acc.x += v0.x; acc.y += v0.y; acc.z += v0.z; acc.w += v0.w;
        }
        float sc = a / fmaxf((float)(e - s), 1.f);
        acc.x *= sc; acc.y *= sc; acc.z *= sc; acc.w *= sc;
        *(float4*)(g_agg1 + (size_t)gw * DD + base) = acc;
    }
}

// ---------------- TF32 tensor-core layer GEMM ----------------
// C(128x128 tile) = [h|agg0|agg1](Mx384) @ [Wself;Wstd;Wdts](384x128)
// 256 threads = 8 warps (4 warp-rows x 2 warp-cols), warp tile 32x64,
// mma.sync.m16n8k8.tf32. Epilogue: +bias, relu, write h, JK-max.

__device__ __forceinline__ unsigned f2tf(float x) {
    unsigned r;
    asm("cvt.rna.tf32.f32 %0, %1;" : "=r"(r) : "f"(x));
    return r;
}

#define AS_STRIDE 20
#define BS_STRIDE 132

__global__ __launch_bounds__(256) void gemm_layer_tc(
    const float* __restrict__ A0,
    const float* __restrict__ B0,
    const float* __restrict__ B1,
    const float* __restrict__ B2,
    const float* __restrict__ bs0,
    const float* __restrict__ bs1,
    const float* __restrict__ bs2,
    const float* __restrict__ alpha,
    float* __restrict__ Hout,
    int firstLayer, int M)
{
    __shared__ __align__(16) unsigned As[128 * AS_STRIDE];
    __shared__ __align__(16) unsigned Bs[16 * BS_STRIDE];
    __shared__ float bias_s[DD];

    int tid = threadIdx.x;
    int block_row = blockIdx.x * 128;

    int warpId = tid >> 5;
    int lane = tid & 31;
    int g = lane >> 2;     // group 0..7
    int t = lane & 3;      // thread in group 0..3
    int warp_row = warpId & 3;   // 0..3 -> 32 rows each
    int warp_col = warpId >> 2;  // 0..1 -> 64 cols each

    if (tid < DD) {
        float a = alpha[0];
        bias_s[tid] = bs0[tid] + (1.f - a) * bs1[tid] + a * bs2[tid];
    }

    float acc[2][8][4];
    #pragma unroll
    for (int mt = 0; mt < 2; mt++)
        #pragma unroll
        for (int nt = 0; nt < 8; nt++)
            #pragma unroll
            for (int r = 0; r < 4; r++) acc[mt][nt][r] = 0.f;

    const float* Aseg[3] = { A0, g_agg0, g_agg1 };
    const float* Bseg[3] = { B0, B1, B2 };

    int a_row = tid >> 2;        // 0..63 (also +64)
    int a_k4 = (tid & 3) * 4;

    #pragma unroll 1
    for (int chunk = 0; chunk < 24; chunk++) {
        int seg = chunk >> 3;
        int kl = (chunk & 7) * 16;
        const float* A = Aseg[seg];
        const float* B = Bseg[seg];

        // A tile: 128 rows x 16 k -> As[m*20 + k] (tf32)
        #pragma unroll
        for (int half = 0; half < 2; half++) {
            int row = a_row + half * 64;
            int gr = block_row + row;
            float4 av = make_float4(0.f, 0.f, 0.f, 0.f);
            if (gr < M) av = *(const float4*)(A + (size_t)gr * DD + kl + a_k4);
            uint4 u;
            u.x = f2tf(av.x); u.y = f2tf(av.y); u.z = f2tf(av.z); u.w = f2tf(av.w);
            *(uint4*)&As[row * AS_STRIDE + a_k4] = u;
        }
        // B tile: 16 k x 128 n -> Bs[k*132 + n] (tf32)
        #pragma unroll
        for (int i = 0; i < 2; i++) {
            int idx = tid + i * 256;
            int k = idx >> 5;
            int n4 = (idx & 31) * 4;
            float4 bv = *(const float4*)(B + (size_t)(kl + k) * DD + n4);
            uint4 u;
            u.x = f2tf(bv.x); u.y = f2tf(bv.y); u.z = f2tf(bv.z); u.w = f2tf(bv.w);
            *(uint4*)&Bs[k * BS_STRIDE + n4] = u;
        }
        __syncthreads();

        #pragma unroll
        for (int ks = 0; ks < 2; ks++) {
            int k0 = ks * 8;
            unsigned af[2][4];
            #pragma unroll
            for (int mt = 0; mt < 2; mt++) {
                int mrow = warp_row * 32 + mt * 16;
                af[mt][0] = As[(mrow + g) * AS_STRIDE + k0 + t];
                af[mt][1] = As[(mrow + g + 8) * AS_STRIDE + k0 + t];
                af[mt][2] = As[(mrow + g) * AS_STRIDE + k0 + t + 4];
                af[mt][3] = As[(mrow + g + 8) * AS_STRIDE + k0 + t + 4];
            }
            unsigned bf[8][2];
            #pragma unroll
            for (int nt = 0; nt < 8; nt++) {
                int ncol = warp_col * 64 + nt * 8 + g;
                bf[nt][0] = Bs[(k0 + t) * BS_STRIDE + ncol];
                bf[nt][1] = Bs[(k0 + t + 4) * BS_STRIDE + ncol];
            }
            #pragma unroll
            for (int mt = 0; mt < 2; mt++)
                #pragma unroll
                for (int nt = 0; nt < 8; nt++) {
                    asm volatile(
                        "mma.sync.aligned.m16n8k8.row.col.f32.tf32.tf32.f32 "
                        "{%0,%1,%2,%3}, {%4,%5,%6,%7}, {%8,%9}, {%0,%1,%2,%3};"
                        : "+f"(acc[mt][nt][0]), "+f"(acc[mt][nt][1]),
                          "+f"(acc[mt][nt][2]), "+f"(acc[mt][nt][3])
                        : "r"(af[mt][0]), "r"(af[mt][1]), "r"(af[mt][2]), "r"(af[mt][3]),
                          "r"(bf[nt][0]), "r"(bf[nt][1]));
                }
        }
        __syncthreads();
    }

    // epilogue: bias + relu + store h + JK max
    #pragma unroll
    for (int mt = 0; mt < 2; mt++) {
        #pragma unroll
        for (int nt = 0; nt < 8; nt++) {
            int c0 = warp_col * 64 + nt * 8 + t * 2;
            float b0v = bias_s[c0];
            float b1v = bias_s[c0 + 1];
            #pragma unroll
            for (int rr = 0; rr < 2; rr++) {
                int r = block_row + warp_row * 32 + mt * 16 + g + rr * 8;
                if (r < M) {
                    float v0 = fmaxf(acc[mt][nt][rr * 2 + 0] + b0v, 0.f);
                    float v1 = fmaxf(acc[mt][nt][rr * 2 + 1] + b1v, 0.f);
                    float2 hv = make_float2(v0, v1);
                    *(float2*)(Hout + (size_t)r * DD + c0) = hv;
                    float2* mp = (float2*)(g_hmax + (size_t)r * DD + c0);
                    if (firstLayer) {
                        *mp = hv;
                    } else {
                        float2 mo = *mp;
                        mo.x = fmaxf(mo.x, v0);
                        mo.y = fmaxf(mo.y, v1);
                        *mp = mo;
                    }
                }
            }
        }
    }
}

// ---------------- final linear: hmax (Mx128) @ Wlin (128x64) + blin ----------------
__global__ __launch_bounds__(256) void final_gemm_kernel(
    const float* __restrict__ W, const float* __restrict__ b,
    float* __restrict__ out, int M)
{
    __shared__ __align__(16) float Ws[DD * OO];
    __shared__ __align__(16) float As[16][DD];

    int tid = threadIdx.x;
    for (int i = tid; i < DD * OO / 4; i += 256)
        ((float4*)Ws)[i] = ((const float4*)W)[i];

    int row0 = blockIdx.x * 16;
    for (int i = tid; i < 16 * DD / 4; i += 256) {
        int r = i / 32;
        int c4 = i % 32;
        int gr = row0 + r;
        float4 v = make_float4(0.f, 0.f, 0.f, 0.f);
        if (gr < M) v = ((const float4*)(g_hmax + (size_t)gr * DD))[c4];
        ((float4*)&As[r][0])[c4] = v;
    }
    __syncthreads();

    int col = tid & 63;
    int rgrp = tid >> 6;
    float acc[4] = { 0.f, 0.f, 0.f, 0.f };
    #pragma unroll 4
    for (int k = 0; k < DD; k++) {
        float w = Ws[k * OO + col];
        #pragma unroll
        for (int i = 0; i < 4; i++)
            acc[i] += As[rgrp + i * 4][k] * w;
    }
    float bb = b[col];
    #pragma unroll
    for (int i = 0; i < 4; i++) {
        int r = row0 + rgrp + i * 4;
        if (r < M) out[(size_t)r * OO + col] = acc[i] + bb;
    }
}

// ---------------- launch ----------------
extern "C" void kernel_launch(void* const* d_in, const int* in_sizes, int n_in,
                              void* d_out, int out_size) {
    const float* x     = (const float*)d_in[0];
    const int*   ei    = (const int*)d_in[1];
    const float* Wself = (const float*)d_in[2];
    const float* bself = (const float*)d_in[3];
    const float* Wstd  = (const float*)d_in[4];
    const float* bstd  = (const float*)d_in[5];
    const float* Wdts  = (const float*)d_in[6];
    const float* bdts  = (const float*)d_in[7];
    const float* Wlin  = (const float*)d_in[8];
    const float* blin  = (const float*)d_in[9];
    const float* alpha = (const float*)d_in[10];

    int M = in_sizes[0] / DD;        // 50000
    int E = in_sizes[1] / 2;         // 800000

    float* h0; cudaGetSymbolAddress((void**)&h0, g_h0);
    float* h1; cudaGetSymbolAddress((void**)&h1, g_h1);

    // CSR build
    zero_deg_kernel<<<(M + 255) / 256, 256>>>(M);
    count_kernel<<<(E + 255) / 256, 256>>>(ei, E);
    scan_kernel<<<2, 1024>>>(M);
    fill_kernel<<<(E + 255) / 256, 256>>>(ei, E);

    // layers
    const float* cur = x;
    float* bufs[2] = { h0, h1 };
    int gemm_grid = (M + 127) / 128;
    int agg_grid = (M * 32 + 255) / 256;   // one warp per node
    for (int l = 0; l < LL; l++) {
        agg_kernel<<<agg_grid, 256>>>(cur, alpha, M);
        float* outb = bufs[l & 1];
        gemm_layer_tc<<<gemm_grid, 256>>>(
            cur,
            Wself + (size_t)l * DD * DD,
            Wstd  + (size_t)l * DD * DD,
            Wdts  + (size_t)l * DD * DD,
            bself + (size_t)l * DD,
            bstd  + (size_t)l * DD,
            bdts  + (size_t)l * DD,
            alpha, outb, (l == 0) ? 1 : 0, M);
        cur = outb;
    }

    // final linear
    final_gemm_kernel<<<(M + 15) / 16, 256>>>(Wlin, blin, (float*)d_out, M);
}

// round 3
// speedup vs baseline: 2.4317x; 1.7081x over previous
#include <cuda_runtime.h>
#include <cuda_fp16.h>
#include <cuda_bf16.h>

#define NN 50000
#define EE 800000
#define DD 128
#define OO 64
#define LL 3

// ---------------- scratch (device globals) ----------------
__device__ __half g_hx[NN * DD];      // x converted to fp16
__device__ __half g_h0[NN * DD];
__device__ __half g_h1[NN * DD];
__device__ __half g_agg0[NN * DD];    // (1-a)/deg * sum_{src->dst}
__device__ __half g_agg1[NN * DD];    // a/deg * sum_{dst->src}
__device__ __half g_hmax[NN * DD];
__device__ __half g_Wt[LL * 3 * DD * DD];   // weights fp16, transposed [mat][n][k]

__device__ int g_deg0[NN];
__device__ int g_deg1[NN];
__device__ int g_rp0[NN + 1];
__device__ int g_rp1[NN + 1];
__device__ int g_cur0[NN];
__device__ int g_cur1[NN];
__device__ int g_col0[EE];            // CSR by dst, values = src
__device__ int g_col1[EE];            // CSR by src, values = dst

// ---------------- prep: convert x, transpose+convert weights ----------------
__global__ void convert_x_kernel(const float* __restrict__ x, int total4) {
    int i = blockIdx.x * blockDim.x + threadIdx.x;
    if (i >= total4) return;
    float4 v = ((const float4*)x)[i];
    __half2 h0 = __floats2half2_rn(v.x, v.y);
    __half2 h1 = __floats2half2_rn(v.z, v.w);
    uint2 u;
    u.x = *(unsigned*)&h0;
    u.y = *(unsigned*)&h1;
    ((uint2*)g_hx)[i] = u;
}

__global__ void prep_weights_kernel(const float* __restrict__ Wself,
                                    const float* __restrict__ Wstd,
                                    const float* __restrict__ Wdts) {
    int idx = blockIdx.x * blockDim.x + threadIdx.x;   // over 9*16384
    if (idx >= LL * 3 * DD * DD) return;
    int mat = idx >> 14;          // l*3+s
    int r = (idx >> 7) & 127;     // k (input dim)
    int c = idx & 127;            // n (output dim)
    int l = mat / 3, s = mat % 3;
    const float* W = (s == 0) ? Wself : (s == 1) ? Wstd : Wdts;
    float v = W[(size_t)l * DD * DD + r * DD + c];
    g_Wt[(size_t)mat * DD * DD + c * DD + r] = __float2half(v);
}

// ---------------- CSR build ----------------
__global__ void zero_deg_kernel(int n) {
    int i = blockIdx.x * blockDim.x + threadIdx.x;
    if (i < n) { g_deg0[i] = 0; g_deg1[i] = 0; }
}

__global__ void count_kernel(const int* __restrict__ ei, int E) {
    int e = blockIdx.x * blockDim.x + threadIdx.x;
    if (e >= E) return;
    int src = ei[e];
    int dst = ei[E + e];
    atomicAdd(&g_deg0[dst], 1);
    atomicAdd(&g_deg1[src], 1);
}

__global__ void scan_kernel(int n) {
    const int* deg = (blockIdx.x == 0) ? g_deg0 : g_deg1;
    int* rp = (blockIdx.x == 0) ? g_rp0 : g_rp1;
    int* cur = (blockIdx.x == 0) ? g_cur0 : g_cur1;

    __shared__ int sums[1024];
    int t = threadIdx.x;
    int chunk = (n + 1023) / 1024;
    int begin = t * chunk;
    int end = min(begin + chunk, n);
    int s = 0;
    for (int i = begin; i < end; i++) s += deg[i];
    sums[t] = s;
    __syncthreads();
    for (int off = 1; off < 1024; off <<= 1) {
        int v = (t >= off) ? sums[t - off] : 0;
        __syncthreads();
        sums[t] += v;
        __syncthreads();
    }
    int prefix = (t == 0) ? 0 : sums[t - 1];
    for (int i = begin; i < end; i++) {
        rp[i] = prefix;
        cur[i] = prefix;
        prefix += deg[i];
    }
    if (t == 1023) rp[n] = prefix;
}

__global__ void fill_kernel(const int* __restrict__ ei, int E) {
    int e = blockIdx.x * blockDim.x + threadIdx.x;
    if (e >= E) return;
    int src = ei[e];
    int dst = ei[E + e];
    int p0 = atomicAdd(&g_cur0[dst], 1);
    g_col0[p0] = src;
    int p1 = atomicAdd(&g_cur1[src], 1);
    g_col1[p1] = dst;
}

// ---------------- aggregation (fp16): one warp per node ----------------
__global__ void agg_kernel(const __half* __restrict__ h,
                           const float* __restrict__ alpha, int M) {
    int gw = (blockIdx.x * blockDim.x + threadIdx.x) >> 5;
    if (gw >= M) return;
    int lane = threadIdx.x & 31;
    int base = lane * 4;   // halves
    float a = alpha[0];

    #pragma unroll
    for (int dir = 0; dir < 2; dir++) {
        const int* rp = dir ? g_rp1 : g_rp0;
        const int* col = dir ? g_col1 : g_col0;
        __half* out = dir ? g_agg1 : g_agg0;
        float coef = dir ? a : (1.f - a);

        int s = rp[gw], e = rp[gw + 1];
        float4 acc = make_float4(0.f, 0.f, 0.f, 0.f);
        int i = s;
        for (; i + 1 < e; i += 2) {
            int n0 = col[i], n1 = col[i + 1];
            uint2 u0 = *(const uint2*)(h + (size_t)n0 * DD + base);
            uint2 u1 = *(const uint2*)(h + (size_t)n1 * DD + base);
            float2 a0 = __half22float2(*(__half2*)&u0.x);
            float2 a1 = __half22float2(*(__half2*)&u0.y);
            float2 b0 = __half22float2(*(__half2*)&u1.x);
            float2 b1 = __half22float2(*(__half2*)&u1.y);
            acc.x += a0.x + b0.x; acc.y += a0.y + b0.y;
            acc.z += a1.x + b1.x; acc.w += a1.y + b1.y;
        }
        if (i < e) {
            int n0 = col[i];
            uint2 u0 = *(const uint2*)(h + (size_t)n0 * DD + base);
            float2 a0 = __half22float2(*(__half2*)&u0.x);
            float2 a1 = __half22float2(*(__half2*)&u0.y);
            acc.x += a0.x; acc.y += a0.y; acc.z += a1.x; acc.w += a1.y;
        }
        float sc = coef / fmaxf((float)(e - s), 1.f);
        __half2 o0 = __floats2half2_rn(acc.x * sc, acc.y * sc);
        __half2 o1 = __floats2half2_rn(acc.z * sc, acc.w * sc);
        uint2 u;
        u.x = *(unsigned*)&o0;
        u.y = *(unsigned*)&o1;
        *(uint2*)(out + (size_t)gw * DD + base) = u;
    }
}

// ---------------- fp16 tensor-core layer GEMM ----------------
// [h|agg0|agg1](Mx384 fp16) @ Wt(384x128 fp16, pre-transposed [n][k])
// 256 threads = 8 warps (4x2), warp tile 32x64, mma.m16n8k16.f16.f16.f32,
// BK=32, 12 chunks, double-buffered smem, 1 sync/chunk.
#define SA 40   // smem row stride in halves

__global__ __launch_bounds__(256) void gemm_layer_f16(
    const __half* __restrict__ A0,
    const __half* __restrict__ Wt,   // layer base (3 mats)
    const float* __restrict__ bs0,
    const float* __restrict__ bs1,
    const float* __restrict__ bs2,
    const float* __restrict__ alpha,
    __half* __restrict__ Hout,
    int firstLayer, int M)
{
    __shared__ __align__(16) __half As[2][128 * SA];
    __shared__ __align__(16) __half Bs[2][128 * SA];
    __shared__ float bias_s[DD];

    int tid = threadIdx.x;
    int block_row = blockIdx.x * 128;
    int warpId = tid >> 5;
    int lane = tid & 31;
    int g = lane >> 2;
    int t = lane & 3;
    int warp_row = warpId & 3;
    int warp_col = warpId >> 2;

    if (tid < DD) {
        float a = alpha[0];
        bias_s[tid] = bs0[tid] + (1.f - a) * bs1[tid] + a * bs2[tid];
    }

    float acc[2][8][4];
    #pragma unroll
    for (int mt = 0; mt < 2; mt++)
        #pragma unroll
        for (int nt = 0; nt < 8; nt++)
            #pragma unroll
            for (int r = 0; r < 4; r++) acc[mt][nt][r] = 0.f;

    const __half* Aseg[3] = { A0, g_agg0, g_agg1 };

    int l_row = tid >> 2;          // 0..63
    int l_kq = (tid & 3) * 8;      // halves: 0,8,16,24

    uint4 ra[2], rb[2];

    auto load_chunk = [&](int c) {
        int seg = c >> 2;
        int kl = (c & 3) * 32;
        const __half* A = Aseg[seg];
        const __half* B = Wt + (size_t)seg * DD * DD;
        #pragma unroll
        for (int j = 0; j < 2; j++) {
            int row = l_row + j * 64;
            int gr = block_row + row;
            ra[j] = (gr < M) ? *(const uint4*)(A + (size_t)gr * DD + kl + l_kq)
                             : make_uint4(0u, 0u, 0u, 0u);
            rb[j] = *(const uint4*)(B + (size_t)row * DD + kl + l_kq);
        }
    };
    auto store_chunk = [&](int buf) {
        #pragma unroll
        for (int j = 0; j < 2; j++) {
            int row = l_row + j * 64;
            *(uint4*)&As[buf][row * SA + l_kq] = ra[j];
            *(uint4*)&Bs[buf][row * SA + l_kq] = rb[j];
        }
    };

    load_chunk(0);
    store_chunk(0);
    __syncthreads();

    #pragma unroll 1
    for (int c = 0; c < 12; c++) {
        int buf = c & 1;
        if (c < 11) load_chunk(c + 1);

        #pragma unroll
        for (int ks = 0; ks < 2; ks++) {
            int k0 = ks * 16;
            unsigned af[2][4];
            #pragma unroll
            for (int mt = 0; mt < 2; mt++) {
                int mrow = warp_row * 32 + mt * 16;
                const __half* base = &As[buf][0];
                af[mt][0] = *(const unsigned*)&base[(mrow + g) * SA + k0 + 2 * t];
                af[mt][1] = *(const unsigned*)&base[(mrow + g + 8) * SA + k0 + 2 * t];
                af[mt][2] = *(const unsigned*)&base[(mrow + g) * SA + k0 + 8 + 2 * t];
                af[mt][3] = *(const unsigned*)&base[(mrow + g + 8) * SA + k0 + 8 + 2 * t];
            }
            unsigned bf[8][2];
            #pragma unroll
            for (int nt = 0; nt < 8; nt++) {
                int n = warp_col * 64 + nt * 8 + g;
                const __half* base = &Bs[buf][0];
                bf[nt][0] = *(const unsigned*)&base[n * SA + k0 + 2 * t];
                bf[nt][1] = *(const unsigned*)&base[n * SA + k0 + 8 + 2 * t];
            }
            #pragma unroll
            for (int mt = 0; mt < 2; mt++)
                #pragma unroll
                for (int nt = 0; nt < 8; nt++) {
                    asm volatile(
                        "mma.sync.aligned.m16n8k16.row.col.f32.f16.f16.f32 "
                        "{%0,%1,%2,%3}, {%4,%5,%6,%7}, {%8,%9}, {%0,%1,%2,%3};"
                        : "+f"(acc[mt][nt][0]), "+f"(acc[mt][nt][1]),
                          "+f"(acc[mt][nt][2]), "+f"(acc[mt][nt][3])
                        : "r"(af[mt][0]), "r"(af[mt][1]), "r"(af[mt][2]), "r"(af[mt][3]),
                          "r"(bf[nt][0]), "r"(bf[nt][1]));
                }
        }
        if (c < 11) {
            store_chunk(buf ^ 1);
            __syncthreads();
        }
    }

    // epilogue: bias + relu + store h(fp16) + JK max(fp16)
    #pragma unroll
    for (int mt = 0; mt < 2; mt++) {
        #pragma unroll
        for (int nt = 0; nt < 8; nt++) {
            int c0 = warp_col * 64 + nt * 8 + 2 * t;
            float b0v = bias_s[c0];
            float b1v = bias_s[c0 + 1];
            #pragma unroll
            for (int rr = 0; rr < 2; rr++) {
                int r = block_row + warp_row * 32 + mt * 16 + g + rr * 8;
                if (r < M) {
                    float v0 = fmaxf(acc[mt][nt][rr * 2 + 0] + b0v, 0.f);
                    float v1 = fmaxf(acc[mt][nt][rr * 2 + 1] + b1v, 0.f);
                    __half2 hv = __floats2half2_rn(v0, v1);
                    *(__half2*)(Hout + (size_t)r * DD + c0) = hv;
                    __half2* mp = (__half2*)(g_hmax + (size_t)r * DD + c0);
                    if (firstLayer) {
                        *mp = hv;
                    } else {
                        *mp = __hmax2(*mp, hv);
                    }
                }
            }
        }
    }
}

// ---------------- final linear: hmax(fp16, Mx128) @ Wlin(fp32 128x64) + blin ----
__global__ __launch_bounds__(256) void final_gemm_kernel(
    const float* __restrict__ W, const float* __restrict__ b,
    float* __restrict__ out, int M)
{
    __shared__ __align__(16) float Ws[DD * OO];
    __shared__ __align__(16) float As[16][DD];

    int tid = threadIdx.x;
    for (int i = tid; i < DD * OO / 4; i += 256)
        ((float4*)Ws)[i] = ((const float4*)W)[i];

    int row0 = blockIdx.x * 16;
    // 16 rows x 128 halves = 512 uint2 loads
    for (int i = tid; i < 512; i += 256) {
        int r = i >> 5;             // 0..15
        int c4 = (i & 31) * 4;      // halves
        int gr = row0 + r;
        float4 v = make_float4(0.f, 0.f, 0.f, 0.f);
        if (gr < M) {
            uint2 u = *(const uint2*)(g_hmax + (size_t)gr * DD + c4);
            float2 f0 = __half22float2(*(__half2*)&u.x);
            float2 f1 = __half22float2(*(__half2*)&u.y);
            v = make_float4(f0.x, f0.y, f1.x, f1.y);
        }
        *(float4*)&As[r][c4] = v;
    }
    __syncthreads();

    int col = tid & 63;
    int rgrp = tid >> 6;
    float acc[4] = { 0.f, 0.f, 0.f, 0.f };
    #pragma unroll 4
    for (int k = 0; k < DD; k++) {
        float w = Ws[k * OO + col];
        #pragma unroll
        for (int i = 0; i < 4; i++)
            acc[i] += As[rgrp + i * 4][k] * w;
    }
    float bb = b[col];
    #pragma unroll
    for (int i = 0; i < 4; i++) {
        int r = row0 + rgrp + i * 4;
        if (r < M) out[(size_t)r * OO + col] = acc[i] + bb;
    }
}

// ---------------- launch ----------------
extern "C" void kernel_launch(void* const* d_in, const int* in_sizes, int n_in,
                              void* d_out, int out_size) {
    const float* x     = (const float*)d_in[0];
    const int*   ei    = (const int*)d_in[1];
    const float* Wself = (const float*)d_in[2];
    const float* bself = (const float*)d_in[3];
    const float* Wstd  = (const float*)d_in[4];
    const float* bstd  = (const float*)d_in[5];
    const float* Wdts  = (const float*)d_in[6];
    const float* bdts  = (const float*)d_in[7];
    const float* Wlin  = (const float*)d_in[8];
    const float* blin  = (const float*)d_in[9];
    const float* alpha = (const float*)d_in[10];

    int M = in_sizes[0] / DD;        // 50000
    int E = in_sizes[1] / 2;         // 800000

    __half* hx; cudaGetSymbolAddress((void**)&hx, g_hx);
    __half* h0; cudaGetSymbolAddress((void**)&h0, g_h0);
    __half* h1; cudaGetSymbolAddress((void**)&h1, g_h1);
    __half* wt; cudaGetSymbolAddress((void**)&wt, g_Wt);

    // prep
    int total4 = M * DD / 4;
    convert_x_kernel<<<(total4 + 255) / 256, 256>>>(x, total4);
    prep_weights_kernel<<<(LL * 3 * DD * DD + 255) / 256, 256>>>(Wself, Wstd, Wdts);

    // CSR build
    zero_deg_kernel<<<(M + 255) / 256, 256>>>(M);
    count_kernel<<<(E + 255) / 256, 256>>>(ei, E);
    scan_kernel<<<2, 1024>>>(M);
    fill_kernel<<<(E + 255) / 256, 256>>>(ei, E);

    // layers
    const __half* cur = hx;
    __half* bufs[2] = { h0, h1 };
    int gemm_grid = (M + 127) / 128;
    int agg_grid = (M * 32 + 255) / 256;
    for (int l = 0; l < LL; l++) {
        agg_kernel<<<agg_grid, 256>>>(cur, alpha, M);
        __half* outb = bufs[l & 1];
        gemm_layer_f16<<<gemm_grid, 256>>>(
            cur,
            wt + (size_t)l * 3 * DD * DD,
            bself + (size_t)l * DD,
            bstd  + (size_t)l * DD,
            bdts  + (size_t)l * DD,
            alpha, outb, (l == 0) ? 1 : 0, M);
        cur = outb;
    }

    // final linear
    final_gemm_kernel<<<(M + 15) / 16, 256>>>(Wlin, blin, (float*)d_out, M);
}